// round 1
// baseline (speedup 1.0000x reference)
#include <cuda_runtime.h>
#include <cstdint>

#define N_NODES 100000
#define N_EDGES 1600000
#define IN_F 64
#define OUT_F 64
#define SUPPORT 3

// Scratch: Z[k][n][f] = (X @ W_k)[n][f]   (76.8 MB static device array)
__device__ float g_Z[(size_t)SUPPORT * N_NODES * OUT_F];

// ---------------------------------------------------------------------------
// GEMM: Z[k][n][:] = X[n][:] @ W[k*64:(k+1)*64][:]
// Block: 256 threads, 64 rows x 64 cols tile, 4x4 register microtile.
// ---------------------------------------------------------------------------
__global__ __launch_bounds__(256) void gemm_kernel(const float* __restrict__ X,
                                                   const float* __restrict__ W) {
    __shared__ float  Xs[64][64];     // [row][j]
    __shared__ float4 Ws4[64][16];    // [j][col/4]

    const int k     = blockIdx.y;
    const int rbase = blockIdx.x * 64;
    const int tid   = threadIdx.x;

    // Load X tile: 64 rows x 16 float4
    #pragma unroll
    for (int i = tid; i < 64 * 16; i += 256) {
        int r  = i >> 4;
        int c4 = i & 15;
        int gr = rbase + r;
        float4 v = make_float4(0.f, 0.f, 0.f, 0.f);
        if (gr < N_NODES)
            v = *reinterpret_cast<const float4*>(X + (size_t)gr * IN_F + c4 * 4);
        Xs[r][c4 * 4 + 0] = v.x;
        Xs[r][c4 * 4 + 1] = v.y;
        Xs[r][c4 * 4 + 2] = v.z;
        Xs[r][c4 * 4 + 3] = v.w;
    }
    // Load W_k tile: 64 rows (j) x 16 float4 (cols)
    #pragma unroll
    for (int i = tid; i < 64 * 16; i += 256) {
        int j  = i >> 4;
        int c4 = i & 15;
        Ws4[j][c4] = *reinterpret_cast<const float4*>(W + (size_t)(k * 64 + j) * OUT_F + c4 * 4);
    }
    __syncthreads();

    const int ty = tid >> 4;   // row group (0..15), 4 rows each
    const int tx = tid & 15;   // col quad  (0..15), 4 cols each

    float acc[4][4];
    #pragma unroll
    for (int i = 0; i < 4; i++)
        #pragma unroll
        for (int c = 0; c < 4; c++) acc[i][c] = 0.f;

    #pragma unroll
    for (int j = 0; j < 64; j++) {
        float4 b = Ws4[j][tx];
        #pragma unroll
        for (int i = 0; i < 4; i++) {
            float a = Xs[ty * 4 + i][j];
            acc[i][0] += a * b.x;
            acc[i][1] += a * b.y;
            acc[i][2] += a * b.z;
            acc[i][3] += a * b.w;
        }
    }

    float* Zk = g_Z + (size_t)k * N_NODES * OUT_F;
    #pragma unroll
    for (int i = 0; i < 4; i++) {
        int gr = rbase + ty * 4 + i;
        if (gr < N_NODES) {
            float4 o = make_float4(acc[i][0], acc[i][1], acc[i][2], acc[i][3]);
            *reinterpret_cast<float4*>(Zk + (size_t)gr * OUT_F + tx * 4) = o;
        }
    }
}

// ---------------------------------------------------------------------------
// out[n][c] = bias[c]  (init before scatter-add)
// ---------------------------------------------------------------------------
__global__ __launch_bounds__(256) void bias_init_kernel(float* __restrict__ out,
                                                        const float* __restrict__ bias) {
    int idx = blockIdx.x * 256 + threadIdx.x;
    if (idx < N_NODES * OUT_F) out[idx] = __ldg(bias + (idx & 63));
}

// ---------------------------------------------------------------------------
// SpMM scatter: out[row] += val * Z_k[col]   (16 lanes/edge, float4 per lane)
// ---------------------------------------------------------------------------
__global__ __launch_bounds__(256) void spmm_kernel(const int* __restrict__ rows,
                                                   const int* __restrict__ cols,
                                                   const float* __restrict__ vals,
                                                   int k,
                                                   float* __restrict__ out) {
    int t = blockIdx.x * 256 + threadIdx.x;
    int e = t >> 4;            // edge index (16 lanes per edge)
    int lane = t & 15;         // float4 slot within the 64-wide row
    if (e >= N_EDGES) return;

    int   r = __ldg(rows + e);
    int   c = __ldg(cols + e);
    float v = __ldg(vals + e);

    const float* Zk = g_Z + (size_t)k * N_NODES * OUT_F;
    float4 f = *reinterpret_cast<const float4*>(Zk + (size_t)c * OUT_F + lane * 4);

    float4 y = make_float4(v * f.x, v * f.y, v * f.z, v * f.w);
    float* dst = out + (size_t)r * OUT_F + lane * 4;
    asm volatile("red.global.add.v4.f32 [%0], {%1, %2, %3, %4};"
                 :: "l"(dst), "f"(y.x), "f"(y.y), "f"(y.z), "f"(y.w)
                 : "memory");
}

// ---------------------------------------------------------------------------
extern "C" void kernel_launch(void* const* d_in, const int* in_sizes, int n_in,
                              void* d_out, int out_size) {
    const float* X     = (const float*)d_in[0];
    const int*   erows = (const int*)  d_in[1];
    const int*   ecols = (const int*)  d_in[2];
    const float* evals = (const float*)d_in[3];
    const float* W     = (const float*)d_in[4];
    const float* bias  = (const float*)d_in[5];
    float*       out   = (float*)d_out;

    // 1) Z[k] = X @ W_k
    dim3 ggrid((N_NODES + 63) / 64, SUPPORT);
    gemm_kernel<<<ggrid, 256>>>(X, W);

    // 2) out = bias (broadcast)
    bias_init_kernel<<<(N_NODES * OUT_F + 255) / 256, 256>>>(out, bias);

    // 3) out += S_k @ Z_k  for each support (sequential launches keep the
    //    working set Z_k + out ~51 MB, L2-resident)
    int spmm_blocks = (N_EDGES * 16 + 255) / 256;
    for (int k = 0; k < SUPPORT; k++) {
        spmm_kernel<<<spmm_blocks, 256>>>(erows + (size_t)k * N_EDGES,
                                          ecols + (size_t)k * N_EDGES,
                                          evals + (size_t)k * N_EDGES,
                                          k, out);
    }
}

// round 2
// speedup vs baseline: 1.2360x; 1.2360x over previous
#include <cuda_runtime.h>
#include <cstdint>

#define N_NODES 100000
#define N_EDGES 1600000
#define IN_F 64
#define OUT_F 64
#define SUPPORT 3
#define EPG 4   // edges per 16-lane group (batched for MLP)

// Scratch: Z[k][n][f] = (X @ W_k)[n][f]   (76.8 MB static device array)
__device__ float g_Z[(size_t)SUPPORT * N_NODES * OUT_F];

// ---------------------------------------------------------------------------
// GEMM: Z[k][n][:] = X[n][:] @ W[k*64:(k+1)*64][:]
// Block: 256 threads, 64 rows x 64 cols tile, 4x4 register microtile.
// ---------------------------------------------------------------------------
__global__ __launch_bounds__(256) void gemm_kernel(const float* __restrict__ X,
                                                   const float* __restrict__ W) {
    __shared__ float  Xs[64][64];     // [row][j]
    __shared__ float4 Ws4[64][16];    // [j][col/4]

    const int k     = blockIdx.y;
    const int rbase = blockIdx.x * 64;
    const int tid   = threadIdx.x;

    #pragma unroll
    for (int i = tid; i < 64 * 16; i += 256) {
        int r  = i >> 4;
        int c4 = i & 15;
        int gr = rbase + r;
        float4 v = make_float4(0.f, 0.f, 0.f, 0.f);
        if (gr < N_NODES)
            v = *reinterpret_cast<const float4*>(X + (size_t)gr * IN_F + c4 * 4);
        Xs[r][c4 * 4 + 0] = v.x;
        Xs[r][c4 * 4 + 1] = v.y;
        Xs[r][c4 * 4 + 2] = v.z;
        Xs[r][c4 * 4 + 3] = v.w;
    }
    #pragma unroll
    for (int i = tid; i < 64 * 16; i += 256) {
        int j  = i >> 4;
        int c4 = i & 15;
        Ws4[j][c4] = *reinterpret_cast<const float4*>(W + (size_t)(k * 64 + j) * OUT_F + c4 * 4);
    }
    __syncthreads();

    const int ty = tid >> 4;
    const int tx = tid & 15;

    float acc[4][4];
    #pragma unroll
    for (int i = 0; i < 4; i++)
        #pragma unroll
        for (int c = 0; c < 4; c++) acc[i][c] = 0.f;

    #pragma unroll
    for (int j = 0; j < 64; j++) {
        float4 b = Ws4[j][tx];
        #pragma unroll
        for (int i = 0; i < 4; i++) {
            float a = Xs[ty * 4 + i][j];
            acc[i][0] += a * b.x;
            acc[i][1] += a * b.y;
            acc[i][2] += a * b.z;
            acc[i][3] += a * b.w;
        }
    }

    float* Zk = g_Z + (size_t)k * N_NODES * OUT_F;
    #pragma unroll
    for (int i = 0; i < 4; i++) {
        int gr = rbase + ty * 4 + i;
        if (gr < N_NODES) {
            float4 o = make_float4(acc[i][0], acc[i][1], acc[i][2], acc[i][3]);
            *reinterpret_cast<float4*>(Zk + (size_t)gr * OUT_F + tx * 4) = o;
        }
    }
}

// ---------------------------------------------------------------------------
// out[n][c] = bias[c]  (init before scatter-add)
// ---------------------------------------------------------------------------
__global__ __launch_bounds__(256) void bias_init_kernel(float* __restrict__ out,
                                                        const float* __restrict__ bias) {
    int idx = blockIdx.x * 256 + threadIdx.x;
    if (idx < N_NODES * OUT_F) out[idx] = __ldg(bias + (idx & 63));
}

// ---------------------------------------------------------------------------
// Fused SpMM scatter over all 3 supports, 4 edges per thread for MLP.
// Thread layout: group g = t>>4 (16 lanes per group, lane = float4 slot).
// Group g handles global edges [4g, 4g+4) in the flattened [3*N_EDGES] space.
// N_EDGES % EPG == 0, so all EPG edges of a group share the same support k.
// ---------------------------------------------------------------------------
__global__ __launch_bounds__(256) void spmm_fused_kernel(const int* __restrict__ rows,
                                                         const int* __restrict__ cols,
                                                         const float* __restrict__ vals,
                                                         float* __restrict__ out) {
    const int t    = blockIdx.x * 256 + threadIdx.x;
    const int g    = t >> 4;
    const int slot = t & 15;

    const long ge0 = (long)g * EPG;                // first global edge of group
    const int  k   = (int)(ge0 / N_EDGES);         // support index (uniform in group)
    const int  e0  = (int)(ge0 - (long)k * N_EDGES);

    const int*   kr = rows + (size_t)k * N_EDGES;
    const int*   kc = cols + (size_t)k * N_EDGES;
    const float* kv = vals + (size_t)k * N_EDGES;
    const float* Zk = g_Z + (size_t)k * N_NODES * OUT_F;

    // Phase 1: edge metadata (broadcast within 16-lane group, coalesced across groups)
    int   rr[EPG], cc[EPG];
    float vv[EPG];
    #pragma unroll
    for (int j = 0; j < EPG; j++) {
        rr[j] = __ldg(kr + e0 + j);
        cc[j] = __ldg(kc + e0 + j);
        vv[j] = __ldg(kv + e0 + j);
    }

    // Phase 2: 4 independent gathers (MLP=4)
    float4 f[EPG];
    #pragma unroll
    for (int j = 0; j < EPG; j++)
        f[j] = *reinterpret_cast<const float4*>(Zk + (size_t)cc[j] * OUT_F + slot * 4);

    // Phase 3: scale + scatter-add
    #pragma unroll
    for (int j = 0; j < EPG; j++) {
        float4 y = make_float4(vv[j] * f[j].x, vv[j] * f[j].y,
                               vv[j] * f[j].z, vv[j] * f[j].w);
        float* dst = out + (size_t)rr[j] * OUT_F + slot * 4;
        asm volatile("red.global.add.v4.f32 [%0], {%1, %2, %3, %4};"
                     :: "l"(dst), "f"(y.x), "f"(y.y), "f"(y.z), "f"(y.w)
                     : "memory");
    }
}

// ---------------------------------------------------------------------------
extern "C" void kernel_launch(void* const* d_in, const int* in_sizes, int n_in,
                              void* d_out, int out_size) {
    const float* X     = (const float*)d_in[0];
    const int*   erows = (const int*)  d_in[1];
    const int*   ecols = (const int*)  d_in[2];
    const float* evals = (const float*)d_in[3];
    const float* W     = (const float*)d_in[4];
    const float* bias  = (const float*)d_in[5];
    float*       out   = (float*)d_out;

    // 1) Z[k] = X @ W_k
    dim3 ggrid((N_NODES + 63) / 64, SUPPORT);
    gemm_kernel<<<ggrid, 256>>>(X, W);

    // 2) out = bias (broadcast)
    bias_init_kernel<<<(N_NODES * OUT_F + 255) / 256, 256>>>(out, bias);

    // 3) out += S_k @ Z_k, all supports in one launch, 4 edges/thread
    //    total thread-groups = 3*N_EDGES/EPG, 16 threads per group
    long total_threads = (long)SUPPORT * N_EDGES / EPG * 16;
    int  blocks = (int)((total_threads + 255) / 256);
    spmm_fused_kernel<<<blocks, 256>>>(erows, ecols, evals, out);
}